// round 12
// baseline (speedup 1.0000x reference)
#include <cuda_runtime.h>
#include <cuda_bf16.h>
#include <math.h>
#include <stdint.h>

#define NN 50000
#define NE 1600000
#define NF 256
#define NH 128
#define NC 40

// ---------------- scratch (no allocations allowed) ----------------
__device__ float g_dinv[NN];
__device__ int   g_cnt[NN];
__device__ int   g_base[NN];
__device__ int   g_cur[NN];
__device__ int   g_eidx[NE];
__device__ __align__(16) float g_G1[(size_t)NN * NH];   // X @ W1 (unscaled)
__device__ __align__(16) float g_H1[(size_t)NN * NH];
__device__ __align__(16) float g_G2[(size_t)NN * NC];   // H1 @ W2 (unscaled)
__device__ __align__(16) __nv_bfloat16 g_W1h[NF * NH];  // transposed: [n][k] = n*NF+k
__device__ __align__(16) __nv_bfloat16 g_W1l[NF * NH];

static __device__ __forceinline__ uint32_t pkbf(__nv_bfloat16 a, __nv_bfloat16 b) {
    uint16_t ua = *(uint16_t*)&a, ub = *(uint16_t*)&b;
    return (uint32_t)ua | ((uint32_t)ub << 16);
}

static __device__ __forceinline__ void hmma16816(float* c, uint32_t a0, uint32_t a1,
                                                 uint32_t a2, uint32_t a3,
                                                 uint32_t b0, uint32_t b1) {
    asm volatile("mma.sync.aligned.m16n8k16.row.col.f32.bf16.bf16.f32 "
                 "{%0,%1,%2,%3}, {%4,%5,%6,%7}, {%8,%9}, {%0,%1,%2,%3};"
                 : "+f"(c[0]), "+f"(c[1]), "+f"(c[2]), "+f"(c[3])
                 : "r"(a0), "r"(a1), "r"(a2), "r"(a3), "r"(b0), "r"(b1));
}

// ---------------- CSR build (side stream) ----------------
__global__ void k_zero() {
    int v = blockIdx.x * 256 + threadIdx.x;
    if (v < NN) g_cnt[v] = 0;
}
__global__ void k_hist4(const int* __restrict__ dst) {
    int t = blockIdx.x * 256 + threadIdx.x;
    if (t < NE / 4) {
        int4 d = ((const int4*)dst)[t];
        atomicAdd(&g_cnt[d.x], 1);
        atomicAdd(&g_cnt[d.y], 1);
        atomicAdd(&g_cnt[d.z], 1);
        atomicAdd(&g_cnt[d.w], 1);
    }
}
__global__ __launch_bounds__(1024) void k_scan() {
    __shared__ int sums[1024];
    const int tid = threadIdx.x;
    const int CH = (NN + 1023) / 1024;
    const int start = tid * CH;
    const int end = min(start + CH, NN);
    int s = 0;
    for (int i = start; i < end; i++) s += g_cnt[i];
    sums[tid] = s;
    __syncthreads();
    for (int off = 1; off < 1024; off <<= 1) {
        int v = (tid >= off) ? sums[tid - off] : 0;
        __syncthreads();
        sums[tid] += v;
        __syncthreads();
    }
    int run = (tid == 0) ? 0 : sums[tid - 1];
    for (int i = start; i < end; i++) {
        int c = g_cnt[i];
        g_base[i] = run;
        g_cur[i] = run;
        g_dinv[i] = rsqrtf((float)(c + 1));
        run += c;
    }
}
__global__ void k_build4(const int* __restrict__ src, const int* __restrict__ dst) {
    int t = blockIdx.x * 256 + threadIdx.x;
    if (t < NE / 4) {
        int4 s = ((const int4*)src)[t];
        int4 d = ((const int4*)dst)[t];
        int p0 = atomicAdd(&g_cur[d.x], 1);
        int p1 = atomicAdd(&g_cur[d.y], 1);
        int p2 = atomicAdd(&g_cur[d.z], 1);
        int p3 = atomicAdd(&g_cur[d.w], 1);
        g_eidx[p0] = s.x;
        g_eidx[p1] = s.y;
        g_eidx[p2] = s.z;
        g_eidx[p3] = s.w;
    }
}

// ---------------- W1 prep: transpose + bf16 hi/lo split (main stream) ----------------
__global__ void k_prepW(const float* __restrict__ W1) {
    int idx = blockIdx.x * 256 + threadIdx.x;
    if (idx >= NF * NH) return;
    int k = idx >> 7;
    int n = idx & 127;
    float v = W1[idx];                 // W1[k][n]
    __nv_bfloat16 h = __float2bfloat16(v);
    g_W1h[n * NF + k] = h;
    g_W1l[n * NF + k] = __float2bfloat16(v - __bfloat162float(h));
}

// ---------------- GEMM1 (mma.sync bf16, 3-term split): G1 = X @ W1 (unscaled) ----------------
#define SSTR 20
__global__ __launch_bounds__(256) void k_gemm1_mma(const float* __restrict__ x) {
    __shared__ uint32_t uAh[128 * SSTR], uAl[128 * SSTR];
    __shared__ uint32_t uBh[128 * SSTR], uBl[128 * SSTR];

    const int tid = threadIdx.x;
    const int w = tid >> 5;
    const int lane = tid & 31;
    const int g = lane >> 2;
    const int tig = lane & 3;
    const int row0 = blockIdx.x * 128;

    float acc[16][4];
#pragma unroll
    for (int nt = 0; nt < 16; nt++)
#pragma unroll
        for (int i = 0; i < 4; i++) acc[nt][i] = 0.f;

    for (int ch = 0; ch < 8; ch++) {
        const int k0 = ch * 32;
        __syncthreads();
#pragma unroll
        for (int q = 0; q < 4; q++) {
            int idx = tid + q * 256;
            int ar = idx >> 3;
            int aq = idx & 7;
            int gr = min(row0 + ar, NN - 1);
            float4 v = *(const float4*)&x[(size_t)gr * NF + k0 + aq * 4];
            __nv_bfloat16 hx = __float2bfloat16(v.x), hy = __float2bfloat16(v.y);
            __nv_bfloat16 hz = __float2bfloat16(v.z), hw = __float2bfloat16(v.w);
            uint32_t* ph = &uAh[ar * SSTR + aq * 2];
            uint32_t* pl = &uAl[ar * SSTR + aq * 2];
            ph[0] = pkbf(hx, hy);
            ph[1] = pkbf(hz, hw);
            pl[0] = pkbf(__float2bfloat16(v.x - __bfloat162float(hx)),
                         __float2bfloat16(v.y - __bfloat162float(hy)));
            pl[1] = pkbf(__float2bfloat16(v.z - __bfloat162float(hz)),
                         __float2bfloat16(v.w - __bfloat162float(hw)));
        }
#pragma unroll
        for (int q = 0; q < 4; q++) {
            int idx = tid + q * 256;
            int mat = idx >> 9;
            int br = (idx >> 2) & 127;
            int bc = idx & 3;
            const __nv_bfloat16* gsrc = mat ? g_W1l : g_W1h;
            uint4 v = *(const uint4*)&gsrc[(size_t)br * NF + k0 + bc * 8];
            uint32_t* p = (mat ? uBl : uBh) + br * SSTR + bc * 4;
            p[0] = v.x; p[1] = v.y; p[2] = v.z; p[3] = v.w;
        }
        __syncthreads();
#pragma unroll
        for (int ks = 0; ks < 2; ks++) {
            const int ko = ks * 8;
            const int ra0 = (w * 16 + g) * SSTR + tig + ko;
            const int ra1 = (w * 16 + g + 8) * SSTR + tig + ko;
            uint32_t ah0 = uAh[ra0],     ah1 = uAh[ra1];
            uint32_t ah2 = uAh[ra0 + 4], ah3 = uAh[ra1 + 4];
            uint32_t al0 = uAl[ra0],     al1 = uAl[ra1];
            uint32_t al2 = uAl[ra0 + 4], al3 = uAl[ra1 + 4];
#pragma unroll
            for (int nt = 0; nt < 16; nt++) {
                const int rb = (nt * 8 + g) * SSTR + tig + ko;
                uint32_t bh0 = uBh[rb], bh1 = uBh[rb + 4];
                uint32_t bl0 = uBl[rb], bl1 = uBl[rb + 4];
                hmma16816(acc[nt], ah0, ah1, ah2, ah3, bh0, bh1);
                hmma16816(acc[nt], ah0, ah1, ah2, ah3, bl0, bl1);
                hmma16816(acc[nt], al0, al1, al2, al3, bh0, bh1);
            }
        }
    }
    // epilogue: store UNSCALED (dinv applied in agg1 after the stream join)
    const int r0 = row0 + w * 16 + g;
    const int r1 = r0 + 8;
#pragma unroll
    for (int nt = 0; nt < 16; nt++) {
        const int col = nt * 8 + tig * 2;
        if (r0 < NN) {
            float2 o0 = {acc[nt][0], acc[nt][1]};
            *(float2*)&g_G1[(size_t)r0 * NH + col] = o0;
        }
        if (r1 < NN) {
            float2 o1 = {acc[nt][2], acc[nt][3]};
            *(float2*)&g_G1[(size_t)r1 * NH + col] = o1;
        }
    }
}

// ---------------- agg layer1: acc = dinv[v]*g[v] + sum dinv[s]*g[s]; h = relu(dinv[v]*acc+b1)*mask
__global__ __launch_bounds__(128) void k_agg1(const float* __restrict__ b1,
                                              const float* __restrict__ mask) {
    const int v = blockIdx.x;
    const int tid = threadIdx.x;
    const float dvv = g_dinv[v];
    float a0 = dvv * g_G1[(size_t)v * NH + tid];   // self-loop term
    float a1 = 0.f, a2 = 0.f, a3 = 0.f;
    const int beg = g_base[v];
    const int n = g_cnt[v];
    int j = 0;
    for (; j + 4 <= n; j += 4) {
        int s0 = g_eidx[beg + j];
        int s1 = g_eidx[beg + j + 1];
        int s2 = g_eidx[beg + j + 2];
        int s3 = g_eidx[beg + j + 3];
        float d0 = g_dinv[s0], d1 = g_dinv[s1], d2 = g_dinv[s2], d3 = g_dinv[s3];
        a0 = fmaf(g_G1[(size_t)s0 * NH + tid], d0, a0);
        a1 = fmaf(g_G1[(size_t)s1 * NH + tid], d1, a1);
        a2 = fmaf(g_G1[(size_t)s2 * NH + tid], d2, a2);
        a3 = fmaf(g_G1[(size_t)s3 * NH + tid], d3, a3);
    }
    for (; j < n; j++) {
        int s = g_eidx[beg + j];
        a0 = fmaf(g_G1[(size_t)s * NH + tid], g_dinv[s], a0);
    }
    float acc = (a0 + a1) + (a2 + a3);
    float h = fmaxf(fmaf(acc, dvv, b1[tid]), 0.f) * mask[(size_t)v * NH + tid];
    g_H1[(size_t)v * NH + tid] = h;
}

// ---------------- GEMM2: G2 = H1 @ W2 (unscaled) ----------------
__global__ __launch_bounds__(320) void k_gemm2(const float* __restrict__ W2) {
    __shared__ float ws[NH * NC];
    const int tid = threadIdx.x;
    for (int i = tid; i < NH * NC; i += 320) ws[i] = W2[i];
    __syncthreads();

    const int cg = tid % 10;
    const int rg = tid / 10;
    const int row0 = blockIdx.x * 128;

    float acc[4][4];
#pragma unroll
    for (int r = 0; r < 4; r++)
#pragma unroll
        for (int c = 0; c < 4; c++) acc[r][c] = 0.f;

    int grc[4];
#pragma unroll
    for (int r = 0; r < 4; r++) grc[r] = min(row0 + rg + 32 * r, NN - 1);

    for (int k0 = 0; k0 < NH; k0 += 4) {
        float4 hv[4];
#pragma unroll
        for (int r = 0; r < 4; r++)
            hv[r] = *(const float4*)&g_H1[(size_t)grc[r] * NH + k0];
#pragma unroll
        for (int kk = 0; kk < 4; kk++) {
            float4 wv = *(float4*)&ws[(k0 + kk) * NC + cg * 4];
#pragma unroll
            for (int r = 0; r < 4; r++) {
                float xv = (kk == 0) ? hv[r].x : (kk == 1) ? hv[r].y
                         : (kk == 2) ? hv[r].z : hv[r].w;
                acc[r][0] += xv * wv.x; acc[r][1] += xv * wv.y;
                acc[r][2] += xv * wv.z; acc[r][3] += xv * wv.w;
            }
        }
    }
#pragma unroll
    for (int r = 0; r < 4; r++) {
        int gr = row0 + rg + 32 * r;
        if (gr < NN) {
            float4 o;
            o.x = acc[r][0]; o.y = acc[r][1];
            o.z = acc[r][2]; o.w = acc[r][3];
            *(float4*)&g_G2[(size_t)gr * NC + cg * 4] = o;
        }
    }
}

// ---------------- agg layer2 + bias + log_softmax fused ----------------
__global__ __launch_bounds__(256) void k_agg2(const float* __restrict__ b2,
                                              float* __restrict__ out) {
    const int w = (blockIdx.x * blockDim.x + threadIdx.x) >> 5;
    const int lane = threadIdx.x & 31;
    if (w >= NN) return;
    const size_t rb = (size_t)w * NC;
    const bool hi = (lane < NC - 32);
    const float dv = g_dinv[w];

    float a0 = dv * g_G2[rb + lane];                       // self-loop term
    float a1 = hi ? dv * g_G2[rb + 32 + lane] : 0.f;
    float c0 = 0.f, c1 = 0.f;
    const int beg = g_base[w];
    const int n = g_cnt[w];
    int j = 0;
    for (; j + 2 <= n; j += 2) {
        int s0 = g_eidx[beg + j];
        int s1 = g_eidx[beg + j + 1];
        float d0 = g_dinv[s0], d1 = g_dinv[s1];
        size_t sb0 = (size_t)s0 * NC;
        size_t sb1 = (size_t)s1 * NC;
        a0 = fmaf(g_G2[sb0 + lane], d0, a0);
        c0 = fmaf(g_G2[sb1 + lane], d1, c0);
        if (hi) {
            a1 = fmaf(g_G2[sb0 + 32 + lane], d0, a1);
            c1 = fmaf(g_G2[sb1 + 32 + lane], d1, c1);
        }
    }
    if (j < n) {
        int s = g_eidx[beg + j];
        float d = g_dinv[s];
        size_t sb = (size_t)s * NC;
        a0 = fmaf(g_G2[sb + lane], d, a0);
        if (hi) a1 = fmaf(g_G2[sb + 32 + lane], d, a1);
    }
    a0 += c0; a1 += c1;

    float v0 = fmaf(a0, dv, b2[lane]);
    float v1 = hi ? fmaf(a1, dv, b2[32 + lane]) : -1e30f;

    float m = fmaxf(v0, v1);
#pragma unroll
    for (int o = 16; o; o >>= 1) m = fmaxf(m, __shfl_xor_sync(0xFFFFFFFFu, m, o));
    float s = expf(v0 - m) + (hi ? expf(v1 - m) : 0.f);
#pragma unroll
    for (int o = 16; o; o >>= 1) s += __shfl_xor_sync(0xFFFFFFFFu, s, o);
    float l = m + logf(s);
    out[rb + lane] = v0 - l;
    if (hi) out[rb + 32 + lane] = v1 - l;
}

// ---------------- fork-join resources (created pre-baseline in static init) ----------------
static cudaStream_t g_s = 0;
static cudaEvent_t g_e0 = 0, g_e1 = 0;
static struct GcnInit {
    GcnInit() {
        if (cudaStreamCreateWithFlags(&g_s, cudaStreamNonBlocking) != cudaSuccess) { g_s = 0; return; }
        if (cudaEventCreateWithFlags(&g_e0, cudaEventDisableTiming) != cudaSuccess) { g_e0 = 0; return; }
        if (cudaEventCreateWithFlags(&g_e1, cudaEventDisableTiming) != cudaSuccess) { g_e1 = 0; }
    }
} g_gcn_init;

// ---------------- launch ----------------
extern "C" void kernel_launch(void* const* d_in, const int* in_sizes, int n_in,
                              void* d_out, int out_size) {
    const float* x    = (const float*)d_in[0];
    const int*   ei   = (const int*)d_in[1];
    const float* W1   = (const float*)d_in[2];
    const float* b1   = (const float*)d_in[3];
    const float* W2   = (const float*)d_in[4];
    const float* b2   = (const float*)d_in[5];
    const float* mask = (const float*)d_in[6];
    float*       out  = (float*)d_out;

    const int* src = ei;
    const int* dst = ei + NE;

    // Fork CSR chain onto side stream (GEMM chain no longer reads g_dinv).
    bool fork = (g_s != 0) && (g_e0 != 0) && (g_e1 != 0);
    if (fork) fork = (cudaEventRecord(g_e0, 0) == cudaSuccess);
    if (fork) fork = (cudaStreamWaitEvent(g_s, g_e0, 0) == cudaSuccess);
    cudaStream_t cs = fork ? g_s : 0;

    // CSR chain: cnt/base/cur/eidx/dinv — consumed only after the join.
    k_zero   <<<(NN + 255) / 256, 256, 0, cs>>>();
    k_hist4  <<<(NE / 4 + 255) / 256, 256, 0, cs>>>(dst);
    k_scan   <<<1, 1024, 0, cs>>>();
    k_build4 <<<(NE / 4 + 255) / 256, 256, 0, cs>>>(src, dst);

    // GEMM chain: touches only x, W1, g_W1h/l, g_G1.
    k_prepW     <<<(NF * NH + 255) / 256, 256>>>(W1);
    k_gemm1_mma <<<(NN + 127) / 128, 256>>>(x);

    // join: agg1 needs CSR + dinv + G1
    if (fork) {
        cudaEventRecord(g_e1, g_s);
        cudaStreamWaitEvent(0, g_e1, 0);
    }

    k_agg1  <<<NN, 128>>>(b1, mask);
    k_gemm2 <<<(NN + 127) / 128, 320>>>(W2);
    k_agg2  <<<(NN * 32 + 255) / 256, 256>>>(b2, out);
}

// round 13
// speedup vs baseline: 1.3903x; 1.3903x over previous
#include <cuda_runtime.h>
#include <cuda_bf16.h>
#include <math.h>
#include <stdint.h>

#define NN 50000
#define NE 1600000
#define NF 256
#define NH 128
#define NC 40

// ---------------- scratch (no allocations allowed) ----------------
__device__ float g_dinv[NN];    // main-stream product
__device__ int   g_deg[NN];     // main-stream histogram (self-loop incl.)
__device__ int   g_cnt[NN];     // side-stream histogram
__device__ int   g_base[NN];
__device__ int   g_cur[NN];
__device__ int   g_eidx[NE];
__device__ __align__(16) float g_G1[(size_t)NN * NH];   // dinv * (X @ W1)
__device__ __align__(16) float g_H1[(size_t)NN * NH];
__device__ __align__(16) float g_G2[(size_t)NN * NC];   // dinv * (H1 @ W2)
__device__ __align__(16) __nv_bfloat16 g_W1h[NF * NH];  // transposed: [n][k] = n*NF+k
__device__ __align__(16) __nv_bfloat16 g_W1l[NF * NH];

static __device__ __forceinline__ uint32_t pkbf(__nv_bfloat16 a, __nv_bfloat16 b) {
    uint16_t ua = *(uint16_t*)&a, ub = *(uint16_t*)&b;
    return (uint32_t)ua | ((uint32_t)ub << 16);
}

static __device__ __forceinline__ void hmma16816(float* c, uint32_t a0, uint32_t a1,
                                                 uint32_t a2, uint32_t a3,
                                                 uint32_t b0, uint32_t b1) {
    asm volatile("mma.sync.aligned.m16n8k16.row.col.f32.bf16.bf16.f32 "
                 "{%0,%1,%2,%3}, {%4,%5,%6,%7}, {%8,%9}, {%0,%1,%2,%3};"
                 : "+f"(c[0]), "+f"(c[1]), "+f"(c[2]), "+f"(c[3])
                 : "r"(a0), "r"(a1), "r"(a2), "r"(a3), "r"(b0), "r"(b1));
}

// ================= MAIN-STREAM degree/dinv chain =================
__global__ void k_zerodeg() {
    int v = blockIdx.x * 256 + threadIdx.x;
    if (v < NN) g_deg[v] = 1;            // self-loop
}
__global__ void k_histdeg(const int* __restrict__ dst) {
    int t = blockIdx.x * 256 + threadIdx.x;
    if (t < NE / 4) {
        int4 d = ((const int4*)dst)[t];
        atomicAdd(&g_deg[d.x], 1);
        atomicAdd(&g_deg[d.y], 1);
        atomicAdd(&g_deg[d.z], 1);
        atomicAdd(&g_deg[d.w], 1);
    }
}
__global__ void k_dinv() {
    int v = blockIdx.x * 256 + threadIdx.x;
    if (v < NN) g_dinv[v] = rsqrtf((float)g_deg[v]);
}

// ================= SIDE-STREAM CSR chain (structure only) =================
__global__ void k_zero() {
    int v = blockIdx.x * 256 + threadIdx.x;
    if (v < NN) g_cnt[v] = 0;
}
__global__ void k_hist4(const int* __restrict__ dst) {
    int t = blockIdx.x * 256 + threadIdx.x;
    if (t < NE / 4) {
        int4 d = ((const int4*)dst)[t];
        atomicAdd(&g_cnt[d.x], 1);
        atomicAdd(&g_cnt[d.y], 1);
        atomicAdd(&g_cnt[d.z], 1);
        atomicAdd(&g_cnt[d.w], 1);
    }
}
__global__ __launch_bounds__(1024) void k_scan() {
    __shared__ int sums[1024];
    const int tid = threadIdx.x;
    const int CH = (NN + 1023) / 1024;
    const int start = tid * CH;
    const int end = min(start + CH, NN);
    int s = 0;
    for (int i = start; i < end; i++) s += g_cnt[i];
    sums[tid] = s;
    __syncthreads();
    for (int off = 1; off < 1024; off <<= 1) {
        int v = (tid >= off) ? sums[tid - off] : 0;
        __syncthreads();
        sums[tid] += v;
        __syncthreads();
    }
    int run = (tid == 0) ? 0 : sums[tid - 1];
    for (int i = start; i < end; i++) {
        int c = g_cnt[i];
        g_base[i] = run;
        g_cur[i] = run;
        run += c;
    }
}
__global__ void k_build4(const int* __restrict__ src, const int* __restrict__ dst) {
    int t = blockIdx.x * 256 + threadIdx.x;
    if (t < NE / 4) {
        int4 s = ((const int4*)src)[t];
        int4 d = ((const int4*)dst)[t];
        int p0 = atomicAdd(&g_cur[d.x], 1);
        int p1 = atomicAdd(&g_cur[d.y], 1);
        int p2 = atomicAdd(&g_cur[d.z], 1);
        int p3 = atomicAdd(&g_cur[d.w], 1);
        g_eidx[p0] = s.x;
        g_eidx[p1] = s.y;
        g_eidx[p2] = s.z;
        g_eidx[p3] = s.w;
    }
}

// ---------------- W1 prep: transpose + bf16 hi/lo split (main stream) ----------------
__global__ void k_prepW(const float* __restrict__ W1) {
    int idx = blockIdx.x * 256 + threadIdx.x;
    if (idx >= NF * NH) return;
    int k = idx >> 7;
    int n = idx & 127;
    float v = W1[idx];                 // W1[k][n]
    __nv_bfloat16 h = __float2bfloat16(v);
    g_W1h[n * NF + k] = h;
    g_W1l[n * NF + k] = __float2bfloat16(v - __bfloat162float(h));
}

// ---------------- GEMM1 (mma.sync bf16, 3-term split): G1 = dinv * (X @ W1) ----------------
#define SSTR 20
__global__ __launch_bounds__(256) void k_gemm1_mma(const float* __restrict__ x) {
    __shared__ uint32_t uAh[128 * SSTR], uAl[128 * SSTR];
    __shared__ uint32_t uBh[128 * SSTR], uBl[128 * SSTR];

    const int tid = threadIdx.x;
    const int w = tid >> 5;
    const int lane = tid & 31;
    const int g = lane >> 2;
    const int tig = lane & 3;
    const int row0 = blockIdx.x * 128;

    float acc[16][4];
#pragma unroll
    for (int nt = 0; nt < 16; nt++)
#pragma unroll
        for (int i = 0; i < 4; i++) acc[nt][i] = 0.f;

    for (int ch = 0; ch < 8; ch++) {
        const int k0 = ch * 32;
        __syncthreads();
#pragma unroll
        for (int q = 0; q < 4; q++) {
            int idx = tid + q * 256;
            int ar = idx >> 3;
            int aq = idx & 7;
            int gr = min(row0 + ar, NN - 1);
            float4 v = *(const float4*)&x[(size_t)gr * NF + k0 + aq * 4];
            __nv_bfloat16 hx = __float2bfloat16(v.x), hy = __float2bfloat16(v.y);
            __nv_bfloat16 hz = __float2bfloat16(v.z), hw = __float2bfloat16(v.w);
            uint32_t* ph = &uAh[ar * SSTR + aq * 2];
            uint32_t* pl = &uAl[ar * SSTR + aq * 2];
            ph[0] = pkbf(hx, hy);
            ph[1] = pkbf(hz, hw);
            pl[0] = pkbf(__float2bfloat16(v.x - __bfloat162float(hx)),
                         __float2bfloat16(v.y - __bfloat162float(hy)));
            pl[1] = pkbf(__float2bfloat16(v.z - __bfloat162float(hz)),
                         __float2bfloat16(v.w - __bfloat162float(hw)));
        }
#pragma unroll
        for (int q = 0; q < 4; q++) {
            int idx = tid + q * 256;
            int mat = idx >> 9;
            int br = (idx >> 2) & 127;
            int bc = idx & 3;
            const __nv_bfloat16* gsrc = mat ? g_W1l : g_W1h;
            uint4 v = *(const uint4*)&gsrc[(size_t)br * NF + k0 + bc * 8];
            uint32_t* p = (mat ? uBl : uBh) + br * SSTR + bc * 4;
            p[0] = v.x; p[1] = v.y; p[2] = v.z; p[3] = v.w;
        }
        __syncthreads();
#pragma unroll
        for (int ks = 0; ks < 2; ks++) {
            const int ko = ks * 8;
            const int ra0 = (w * 16 + g) * SSTR + tig + ko;
            const int ra1 = (w * 16 + g + 8) * SSTR + tig + ko;
            uint32_t ah0 = uAh[ra0],     ah1 = uAh[ra1];
            uint32_t ah2 = uAh[ra0 + 4], ah3 = uAh[ra1 + 4];
            uint32_t al0 = uAl[ra0],     al1 = uAl[ra1];
            uint32_t al2 = uAl[ra0 + 4], al3 = uAl[ra1 + 4];
#pragma unroll
            for (int nt = 0; nt < 16; nt++) {
                const int rb = (nt * 8 + g) * SSTR + tig + ko;
                uint32_t bh0 = uBh[rb], bh1 = uBh[rb + 4];
                uint32_t bl0 = uBl[rb], bl1 = uBl[rb + 4];
                hmma16816(acc[nt], ah0, ah1, ah2, ah3, bh0, bh1);
                hmma16816(acc[nt], ah0, ah1, ah2, ah3, bl0, bl1);
                hmma16816(acc[nt], al0, al1, al2, al3, bh0, bh1);
            }
        }
    }
    // epilogue: scale by dinv (produced on THIS stream by k_dinv) and store
    const int r0 = row0 + w * 16 + g;
    const int r1 = r0 + 8;
    const float dv0 = (r0 < NN) ? g_dinv[r0] : 0.f;
    const float dv1 = (r1 < NN) ? g_dinv[r1] : 0.f;
#pragma unroll
    for (int nt = 0; nt < 16; nt++) {
        const int col = nt * 8 + tig * 2;
        if (r0 < NN) {
            float2 o0 = {acc[nt][0] * dv0, acc[nt][1] * dv0};
            *(float2*)&g_G1[(size_t)r0 * NH + col] = o0;
        }
        if (r1 < NN) {
            float2 o1 = {acc[nt][2] * dv1, acc[nt][3] * dv1};
            *(float2*)&g_G1[(size_t)r1 * NH + col] = o1;
        }
    }
}

// ---------------- agg layer1 (CSR gather) + bias/relu/mask fused (R10 form) ----------------
__global__ __launch_bounds__(128) void k_agg1(const float* __restrict__ b1,
                                              const float* __restrict__ mask) {
    const int v = blockIdx.x;
    const int tid = threadIdx.x;
    float a0 = g_G1[(size_t)v * NH + tid];
    float a1 = 0.f, a2 = 0.f, a3 = 0.f;
    const int beg = g_base[v];
    const int n = g_cnt[v];
    int j = 0;
    for (; j + 4 <= n; j += 4) {
        int s0 = g_eidx[beg + j];
        int s1 = g_eidx[beg + j + 1];
        int s2 = g_eidx[beg + j + 2];
        int s3 = g_eidx[beg + j + 3];
        a0 += g_G1[(size_t)s0 * NH + tid];
        a1 += g_G1[(size_t)s1 * NH + tid];
        a2 += g_G1[(size_t)s2 * NH + tid];
        a3 += g_G1[(size_t)s3 * NH + tid];
    }
    for (; j < n; j++) a0 += g_G1[(size_t)g_eidx[beg + j] * NH + tid];
    float acc = (a0 + a1) + (a2 + a3);
    float h = fmaxf(fmaf(acc, g_dinv[v], b1[tid]), 0.f) * mask[(size_t)v * NH + tid];
    g_H1[(size_t)v * NH + tid] = h;
}

// ---------------- GEMM2: G2 = dinv * (H1 @ W2) (R10 form) ----------------
__global__ __launch_bounds__(320) void k_gemm2(const float* __restrict__ W2) {
    __shared__ float ws[NH * NC];
    const int tid = threadIdx.x;
    for (int i = tid; i < NH * NC; i += 320) ws[i] = W2[i];
    __syncthreads();

    const int cg = tid % 10;
    const int rg = tid / 10;
    const int row0 = blockIdx.x * 128;

    float acc[4][4];
#pragma unroll
    for (int r = 0; r < 4; r++)
#pragma unroll
        for (int c = 0; c < 4; c++) acc[r][c] = 0.f;

    int grc[4];
#pragma unroll
    for (int r = 0; r < 4; r++) grc[r] = min(row0 + rg + 32 * r, NN - 1);

    for (int k0 = 0; k0 < NH; k0 += 4) {
        float4 hv[4];
#pragma unroll
        for (int r = 0; r < 4; r++)
            hv[r] = *(const float4*)&g_H1[(size_t)grc[r] * NH + k0];
#pragma unroll
        for (int kk = 0; kk < 4; kk++) {
            float4 wv = *(float4*)&ws[(k0 + kk) * NC + cg * 4];
#pragma unroll
            for (int r = 0; r < 4; r++) {
                float xv = (kk == 0) ? hv[r].x : (kk == 1) ? hv[r].y
                         : (kk == 2) ? hv[r].z : hv[r].w;
                acc[r][0] += xv * wv.x; acc[r][1] += xv * wv.y;
                acc[r][2] += xv * wv.z; acc[r][3] += xv * wv.w;
            }
        }
    }
#pragma unroll
    for (int r = 0; r < 4; r++) {
        int gr = row0 + rg + 32 * r;
        if (gr < NN) {
            float dv = g_dinv[gr];
            float4 o;
            o.x = acc[r][0] * dv; o.y = acc[r][1] * dv;
            o.z = acc[r][2] * dv; o.w = acc[r][3] * dv;
            *(float4*)&g_G2[(size_t)gr * NC + cg * 4] = o;
        }
    }
}

// ---------------- agg layer2 (CSR gather) + bias + log_softmax fused (R10 form) ----------------
__global__ __launch_bounds__(256) void k_agg2(const float* __restrict__ b2,
                                              float* __restrict__ out) {
    const int w = (blockIdx.x * blockDim.x + threadIdx.x) >> 5;
    const int lane = threadIdx.x & 31;
    if (w >= NN) return;
    const size_t rb = (size_t)w * NC;
    const bool hi = (lane < NC - 32);

    float a0 = g_G2[rb + lane];
    float a1 = hi ? g_G2[rb + 32 + lane] : 0.f;
    float c0 = 0.f, c1 = 0.f;
    const int beg = g_base[w];
    const int n = g_cnt[w];
    int j = 0;
    for (; j + 2 <= n; j += 2) {
        size_t sb0 = (size_t)g_eidx[beg + j] * NC;
        size_t sb1 = (size_t)g_eidx[beg + j + 1] * NC;
        a0 += g_G2[sb0 + lane];
        c0 += g_G2[sb1 + lane];
        if (hi) { a1 += g_G2[sb0 + 32 + lane]; c1 += g_G2[sb1 + 32 + lane]; }
    }
    if (j < n) {
        size_t sb = (size_t)g_eidx[beg + j] * NC;
        a0 += g_G2[sb + lane];
        if (hi) a1 += g_G2[sb + 32 + lane];
    }
    a0 += c0; a1 += c1;

    const float dv = g_dinv[w];
    float v0 = fmaf(a0, dv, b2[lane]);
    float v1 = hi ? fmaf(a1, dv, b2[32 + lane]) : -1e30f;

    float m = fmaxf(v0, v1);
#pragma unroll
    for (int o = 16; o; o >>= 1) m = fmaxf(m, __shfl_xor_sync(0xFFFFFFFFu, m, o));
    float s = expf(v0 - m) + (hi ? expf(v1 - m) : 0.f);
#pragma unroll
    for (int o = 16; o; o >>= 1) s += __shfl_xor_sync(0xFFFFFFFFu, s, o);
    float l = m + logf(s);
    out[rb + lane] = v0 - l;
    if (hi) out[rb + 32 + lane] = v1 - l;
}

// ---------------- fork-join resources (created pre-baseline in static init) ----------------
static cudaStream_t g_s = 0;
static cudaEvent_t g_e0 = 0, g_e1 = 0;
static struct GcnInit {
    GcnInit() {
        if (cudaStreamCreateWithFlags(&g_s, cudaStreamNonBlocking) != cudaSuccess) { g_s = 0; return; }
        if (cudaEventCreateWithFlags(&g_e0, cudaEventDisableTiming) != cudaSuccess) { g_e0 = 0; return; }
        if (cudaEventCreateWithFlags(&g_e1, cudaEventDisableTiming) != cudaSuccess) { g_e1 = 0; }
    }
} g_gcn_init;

// ---------------- launch ----------------
extern "C" void kernel_launch(void* const* d_in, const int* in_sizes, int n_in,
                              void* d_out, int out_size) {
    const float* x    = (const float*)d_in[0];
    const int*   ei   = (const int*)d_in[1];
    const float* W1   = (const float*)d_in[2];
    const float* b1   = (const float*)d_in[3];
    const float* W2   = (const float*)d_in[4];
    const float* b2   = (const float*)d_in[5];
    const float* mask = (const float*)d_in[6];
    float*       out  = (float*)d_out;

    const int* src = ei;
    const int* dst = ei + NE;

    // Fork: side stream builds CSR structure only (cnt/base/cur/eidx).
    bool fork = (g_s != 0) && (g_e0 != 0) && (g_e1 != 0);
    if (fork) fork = (cudaEventRecord(g_e0, 0) == cudaSuccess);
    if (fork) fork = (cudaStreamWaitEvent(g_s, g_e0, 0) == cudaSuccess);
    cudaStream_t cs = fork ? g_s : 0;

    // SIDE: CSR structure
    k_zero   <<<(NN + 255) / 256, 256, 0, cs>>>();
    k_hist4  <<<(NE / 4 + 255) / 256, 256, 0, cs>>>(dst);
    k_scan   <<<1, 1024, 0, cs>>>();
    k_build4 <<<(NE / 4 + 255) / 256, 256, 0, cs>>>(src, dst);

    // MAIN: own dinv (duplicate histogram) -> prepW -> gemm1 (scaled epilogue)
    k_zerodeg <<<(NN + 255) / 256, 256>>>();
    k_histdeg <<<(NE / 4 + 255) / 256, 256>>>(dst);
    k_dinv    <<<(NN + 255) / 256, 256>>>();
    k_prepW     <<<(NF * NH + 255) / 256, 256>>>(W1);
    k_gemm1_mma <<<(NN + 127) / 128, 256>>>(x);

    // join: agg1 needs CSR structure from side stream
    if (fork) {
        cudaEventRecord(g_e1, g_s);
        cudaStreamWaitEvent(0, g_e1, 0);
    }

    k_agg1  <<<NN, 128>>>(b1, mask);
    k_gemm2 <<<(NN + 127) / 128, 320>>>(W2);
    k_agg2  <<<(NN * 32 + 255) / 256, 256>>>(b2, out);
}